// round 2
// baseline (speedup 1.0000x reference)
#include <cuda_runtime.h>
#include <cstdint>

// Problem constants
#define M_ROWS 16384
#define KDIM   2048
#define NC     40      // 20 cls + 20 flow logits
#define NCLS   20
#define TM     128     // rows per CTA tile
#define KC     64      // K chunk
#define THREADS 256
#define NSPLIT 8       // K-splits for the W_enc @ W_cat precompute
#define S_MARGIN 0.31f

typedef unsigned long long ull;

// Scratch (no allocations allowed)
__device__ float g_Wcat[KDIM * NC];
__device__ float g_bias[NC];
__device__ float g_part[NSPLIT][KDIM * NC];
__device__ float g_Wbig[KDIM * NC];

// ---------- packed f32x2 helpers (FFMA2 path: 2x fp32 FMA rate on sm_103a) ----------
__device__ __forceinline__ ull pack2(float a, float b) {
    ull r; asm("mov.b64 %0, {%1, %2};" : "=l"(r) : "f"(a), "f"(b)); return r;
}
__device__ __forceinline__ void unpack2(ull v, float& a, float& b) {
    asm("mov.b64 {%0, %1}, %2;" : "=f"(a), "=f"(b) : "l"(v));
}
__device__ __forceinline__ void fma2(ull& acc, ull a, ull b) {
    asm("fma.rn.f32x2 %0, %1, %2, %0;" : "+l"(acc) : "l"(a), "l"(b));
}

// ---------- shared-memory layout for the GEMM tiles ----------
#define AS_STRIDE 65                       // 64 + 1 pad (conflict-free A reads)
#define AS_BUF (TM * AS_STRIDE)            // 8320 floats per buffer
#define BS_BUF (KC * NC)                   // 2560 floats per buffer
#define SMEM_FLOATS (2 * AS_BUF + 2 * BS_BUF)  // 21760 floats = 87040 B

// Core: C[128 x 40] tile of A[row-major, ld=2048] @ B[k][40], K = NCH*64.
// Thread tile: 2 rows x 10 cols. Double-buffered smem, register prefetch.
template <int NCH>
__device__ __forceinline__ void gemm_tile(
    const float* __restrict__ A,   // tile origin (row 0, k 0 of this tile)
    const float* __restrict__ B,   // [k][40] origin for this tile's K range
    float* sm, int tx,
    ull acc0[5], ull acc1[5])
{
    float* As = sm;
    float* Bs = sm + 2 * AS_BUF;

    const int ld_r = tx >> 4;           // 0..15 (row within 16-row strip)
    const int ld_k = (tx & 15) << 2;    // 0..60 (k offset, float4)
    const int c0   = (tx & 3) * 10;     // col group
    const int rp   = tx >> 2;           // 0..63 -> rows 2rp, 2rp+1

    float4 pa[8];
    float  pb[10];

    // prefetch chunk 0 into registers
#pragma unroll
    for (int i = 0; i < 8; i++)
        pa[i] = *reinterpret_cast<const float4*>(A + (size_t)(ld_r + i * 16) * KDIM + ld_k);
#pragma unroll
    for (int i = 0; i < 10; i++)
        pb[i] = B[tx + i * 256];

    // store chunk 0 -> buffer 0
#pragma unroll
    for (int i = 0; i < 8; i++) {
        int base = (ld_r + i * 16) * AS_STRIDE + ld_k;
        As[base + 0] = pa[i].x; As[base + 1] = pa[i].y;
        As[base + 2] = pa[i].z; As[base + 3] = pa[i].w;
    }
#pragma unroll
    for (int i = 0; i < 10; i++) Bs[tx + i * 256] = pb[i];

#pragma unroll 1
    for (int ch = 0; ch < NCH; ch++) {
        // prefetch next chunk (global -> regs); latency hidden by compute below
        if (ch + 1 < NCH) {
            const int kc = (ch + 1) * KC;
#pragma unroll
            for (int i = 0; i < 8; i++)
                pa[i] = *reinterpret_cast<const float4*>(A + (size_t)(ld_r + i * 16) * KDIM + kc + ld_k);
#pragma unroll
            for (int i = 0; i < 10; i++)
                pb[i] = B[kc * NC + tx + i * 256];
        }
        __syncthreads();  // current buffer's stores visible

        const float* a_ptr = As + (ch & 1) * AS_BUF + (rp * 2) * AS_STRIDE;
        const float* b_ptr = Bs + (ch & 1) * BS_BUF + c0;
#pragma unroll 16
        for (int k = 0; k < KC; k++) {
            float a0v = a_ptr[k];
            float a1v = a_ptr[AS_STRIDE + k];
            ull A0 = pack2(a0v, a0v);
            ull A1 = pack2(a1v, a1v);
            const ull* bp = reinterpret_cast<const ull*>(b_ptr + k * NC);
#pragma unroll
            for (int j = 0; j < 5; j++) {
                ull bb = bp[j];
                fma2(acc0[j], A0, bb);
                fma2(acc1[j], A1, bb);
            }
        }

        if (ch + 1 < NCH) {
            __syncthreads();  // everyone done reading the buffer we overwrite next
            float* as = As + ((ch + 1) & 1) * AS_BUF;
            float* bs = Bs + ((ch + 1) & 1) * BS_BUF;
#pragma unroll
            for (int i = 0; i < 8; i++) {
                int base = (ld_r + i * 16) * AS_STRIDE + ld_k;
                as[base + 0] = pa[i].x; as[base + 1] = pa[i].y;
                as[base + 2] = pa[i].z; as[base + 3] = pa[i].w;
            }
#pragma unroll
            for (int i = 0; i < 10; i++) bs[tx + i * 256] = pb[i];
        }
    }
}

// ---------- k0: gather [W_cls | W_fl] into g_Wcat ----------
__global__ void k0_cat(const float* __restrict__ Wc, const float* __restrict__ Wf) {
    int i = blockIdx.x * 256 + threadIdx.x;
    if (i < KDIM * NC) {
        int j = i / NC, c = i % NC;
        g_Wcat[i] = (c < NCLS) ? Wc[j * NCLS + c] : Wf[j * NCLS + (c - NCLS)];
    }
}

// ---------- k0b: fused bias  b_enc @ Wcat + [b_cls | b_fl] ----------
__global__ void k0_bias(const float* __restrict__ be,
                        const float* __restrict__ Wc, const float* __restrict__ Wf,
                        const float* __restrict__ bc, const float* __restrict__ bf) {
    __shared__ float red[256];
    int c = blockIdx.x;
    int tx = threadIdx.x;
    float acc = 0.f;
    for (int j = tx; j < KDIM; j += 256) {
        float w = (c < NCLS) ? Wc[j * NCLS + c] : Wf[j * NCLS + (c - NCLS)];
        acc += be[j] * w;
    }
    red[tx] = acc;
    __syncthreads();
    for (int s = 128; s > 0; s >>= 1) {
        if (tx < s) red[tx] += red[tx + s];
        __syncthreads();
    }
    if (tx == 0) g_bias[c] = red[0] + ((c < NCLS) ? bc[c] : bf[c - NCLS]);
}

// ---------- k1: partials of W_enc @ Wcat  (16 m-tiles x 8 K-splits = 128 CTAs) ----------
__global__ void __launch_bounds__(256, 1) k1_part(const float* __restrict__ Wenc) {
    extern __shared__ float sm[];
    int tx = threadIdx.x;
    int mt = blockIdx.x & 15;
    int js = blockIdx.x >> 4;   // 0..7, K range [js*256, js*256+256)
    ull acc0[5] = {0, 0, 0, 0, 0}, acc1[5] = {0, 0, 0, 0, 0};
    gemm_tile<4>(Wenc + (size_t)mt * TM * KDIM + js * 256,
                 g_Wcat + (size_t)js * 256 * NC, sm, tx, acc0, acc1);
    int c0 = (tx & 3) * 10;
    int r0 = (tx >> 2) * 2;
    float* dst = g_part[js] + (size_t)(mt * TM + r0) * NC + c0;
#pragma unroll
    for (int j = 0; j < 5; j++) {
        float lo, hi;
        unpack2(acc0[j], lo, hi); dst[2 * j] = lo; dst[2 * j + 1] = hi;
        unpack2(acc1[j], lo, hi); dst[NC + 2 * j] = lo; dst[NC + 2 * j + 1] = hi;
    }
}

// ---------- k2: reduce K-splits -> g_Wbig ----------
__global__ void k2_reduce() {
    int i = blockIdx.x * 256 + threadIdx.x;
    if (i < KDIM * NC) {
        float s = 0.f;
#pragma unroll
        for (int t = 0; t < NSPLIT; t++) s += g_part[t][i];
        g_Wbig[i] = s;
    }
}

// ---------- k3: main GEMM x @ W_big + fused softmax/threshold epilogue ----------
__global__ void __launch_bounds__(256, 1) k3_main(const float* __restrict__ x,
                                                  float* __restrict__ out) {
    extern __shared__ float sm[];
    int tx = threadIdx.x;
    int mt = blockIdx.x;    // 0..127
    ull acc0[5] = {0, 0, 0, 0, 0}, acc1[5] = {0, 0, 0, 0, 0};
    gemm_tile<32>(x + (size_t)mt * TM * KDIM, g_Wbig, sm, tx, acc0, acc1);
    __syncthreads();  // done with smem tiles; reuse as logits

    float* Ls = sm;  // [128][40]
    int c0 = (tx & 3) * 10;
    int r0 = (tx >> 2) * 2;
#pragma unroll
    for (int j = 0; j < 5; j++) {
        float lo, hi;
        unpack2(acc0[j], lo, hi);
        Ls[r0 * NC + c0 + 2 * j]     = lo + g_bias[c0 + 2 * j];
        Ls[r0 * NC + c0 + 2 * j + 1] = hi + g_bias[c0 + 2 * j + 1];
        unpack2(acc1[j], lo, hi);
        Ls[(r0 + 1) * NC + c0 + 2 * j]     = lo + g_bias[c0 + 2 * j];
        Ls[(r0 + 1) * NC + c0 + 2 * j + 1] = hi + g_bias[c0 + 2 * j + 1];
    }
    __syncthreads();

    if (tx < TM) {
        const float* L = Ls + tx * NC;
        // cls softmax
        float mc = L[0];
#pragma unroll
        for (int c = 1; c < NCLS; c++) mc = fmaxf(mc, L[c]);
        float p[NCLS];
        float se = 0.f;
#pragma unroll
        for (int c = 0; c < NCLS; c++) { p[c] = expf(L[c] - mc); se += p[c]; }
        float inv = 1.f / se;
        // flow softmax min (tau)
        float mf = L[NCLS], mn = L[NCLS];
#pragma unroll
        for (int c = NCLS + 1; c < NC; c++) { mf = fmaxf(mf, L[c]); mn = fminf(mn, L[c]); }
        float sf = 0.f;
#pragma unroll
        for (int c = NCLS; c < NC; c++) sf += expf(L[c] - mf);
        float tau = expf(mn - mf) / sf;
        float predicted = inv;  // max softmax prob = exp(0)/se
        float scale = (predicted >= tau + S_MARGIN) ? inv : 0.f;

        float4* o4 = reinterpret_cast<float4*>(out + (size_t)(mt * TM + tx) * NCLS);
#pragma unroll
        for (int q = 0; q < 5; q++)
            o4[q] = make_float4(p[4 * q] * scale, p[4 * q + 1] * scale,
                                p[4 * q + 2] * scale, p[4 * q + 3] * scale);
    }
}

extern "C" void kernel_launch(void* const* d_in, const int* in_sizes, int n_in,
                              void* d_out, int out_size) {
    const float* x    = (const float*)d_in[0];
    const float* Wenc = (const float*)d_in[1];
    const float* benc = (const float*)d_in[2];
    const float* Wcls = (const float*)d_in[3];
    const float* bcls = (const float*)d_in[4];
    const float* Wfl  = (const float*)d_in[5];
    const float* bfl  = (const float*)d_in[6];
    float* out = (float*)d_out;

    const int smem = SMEM_FLOATS * (int)sizeof(float);  // 87040 B > 48K -> opt in
    cudaFuncSetAttribute(k1_part, cudaFuncAttributeMaxDynamicSharedMemorySize, smem);
    cudaFuncSetAttribute(k3_main, cudaFuncAttributeMaxDynamicSharedMemorySize, smem);

    k0_cat<<<(KDIM * NC + 255) / 256, 256>>>(Wcls, Wfl);
    k0_bias<<<NC, 256>>>(benc, Wcls, Wfl, bcls, bfl);
    k1_part<<<128, 256, smem>>>(Wenc);
    k2_reduce<<<(KDIM * NC + 255) / 256, 256>>>();
    k3_main<<<128, 256, smem>>>(x, out);
}

// round 3
// speedup vs baseline: 1.3991x; 1.3991x over previous
#include <cuda_runtime.h>
#include <cstdint>

#define M_ROWS 16384
#define KDIM   2048
#define NC     40
#define NCLS   20
#define TM     128
#define KC     32
#define NSPLIT 8
#define S_MARGIN 0.31f

typedef unsigned long long ull;

__device__ float g_Wcat[KDIM * NC];
__device__ float g_bias[NC];
__device__ float g_part[NSPLIT][KDIM * NC];
__device__ float g_Wbig[KDIM * NC];

// ---------- packed f32x2 helpers ----------
__device__ __forceinline__ ull pack2(float a, float b) {
    ull r; asm("mov.b64 %0, {%1, %2};" : "=l"(r) : "f"(a), "f"(b)); return r;
}
__device__ __forceinline__ void unpack2(ull v, float& a, float& b) {
    asm("mov.b64 {%0, %1}, %2;" : "=f"(a), "=f"(b) : "l"(v));
}
__device__ __forceinline__ void fma2(ull& acc, ull a, ull b) {
    asm("fma.rn.f32x2 %0, %1, %2, %0;" : "+l"(acc) : "l"(a), "l"(b));
}
__device__ __forceinline__ ull add2(ull a, ull b) {
    ull r; asm("add.rn.f32x2 %0, %1, %2;" : "=l"(r) : "l"(a), "l"(b)); return r;
}

// ---------- smem layout ----------
#define AST 34                       // A stride (32 + 2 pad), keeps 8B alignment
#define AS_BUF (TM * AST)            // 4352 floats / buffer
#define BS_BUF (KC * NC)             // 1280 floats / buffer
#define SMEM_FLOATS (2 * AS_BUF + 2 * BS_BUF)   // 11264 floats = 45056 B

// Core: C[128 x 40] = A[128 x NCH*32] @ B[NCH*32 x 40].
// 128 threads; thread tile 2 rows x 20 cols. One barrier per chunk.
template <int NCH>
__device__ __forceinline__ void gemm_core(
    const float* __restrict__ A,   // tile origin, row-major ld=KDIM
    const float* __restrict__ B,   // [k][40] origin
    float* sm, int tx,
    ull accA[10], ull accB[10])
{
    float* As = sm;                    // 2 buffers
    float* Bs = sm + 2 * AS_BUF;       // 2 buffers (16B-aligned: 34816 B offset)

    const int ld_r = tx >> 3;          // 0..15
    const int ld_k = (tx & 7) << 2;    // 0..28
    const int g    = tx & 1;           // col group -> c0 = 20*g
    const int r0   = (tx >> 1) * 2;    // even row; thread owns r0, r0+1
    const int c0   = g * 20;

    float4 pa[8];
    float  pb[10];

    // prefetch + store chunk 0
#pragma unroll
    for (int i = 0; i < 8; i++)
        pa[i] = *reinterpret_cast<const float4*>(A + (size_t)(ld_r + i * 16) * KDIM + ld_k);
#pragma unroll
    for (int i = 0; i < 10; i++)
        pb[i] = B[tx + i * 128];
#pragma unroll
    for (int i = 0; i < 8; i++) {
        int base = (ld_r + i * 16) * AST + ld_k;
        *reinterpret_cast<float2*>(As + base)     = make_float2(pa[i].x, pa[i].y);
        *reinterpret_cast<float2*>(As + base + 2) = make_float2(pa[i].z, pa[i].w);
    }
#pragma unroll
    for (int i = 0; i < 10; i++) Bs[tx + i * 128] = pb[i];
    __syncthreads();

#pragma unroll 1
    for (int ch = 0; ch < NCH; ch++) {
        // prefetch next chunk into regs (latency overlapped with compute)
        if (ch + 1 < NCH) {
            const int kc = (ch + 1) * KC;
#pragma unroll
            for (int i = 0; i < 8; i++)
                pa[i] = *reinterpret_cast<const float4*>(A + (size_t)(ld_r + i * 16) * KDIM + kc + ld_k);
#pragma unroll
            for (int i = 0; i < 10; i++)
                pb[i] = B[kc * NC + tx + i * 128];
        }

        const float* a0 = As + (ch & 1) * AS_BUF + r0 * AST;
        const float* a1 = a0 + AST;
        const float* bp = Bs + (ch & 1) * BS_BUF + c0;

#pragma unroll 4
        for (int k2 = 0; k2 < KC / 2; k2++) {
            float2 Av0 = *reinterpret_cast<const float2*>(a0 + 2 * k2);
            float2 Av1 = *reinterpret_cast<const float2*>(a1 + 2 * k2);
            ull a00 = pack2(Av0.x, Av0.x);   // row r0, k even
            ull a01 = pack2(Av0.y, Av0.y);   // row r0, k odd
            ull a10 = pack2(Av1.x, Av1.x);   // row r0+1, k even
            ull a11 = pack2(Av1.y, Av1.y);   // row r0+1, k odd
            const ulonglong2* b0 = reinterpret_cast<const ulonglong2*>(bp + (2 * k2) * NC);
            const ulonglong2* b1 = reinterpret_cast<const ulonglong2*>(bp + (2 * k2 + 1) * NC);
#pragma unroll
            for (int j = 0; j < 5; j++) {
                ulonglong2 q0 = b0[j];
                fma2(accA[2 * j],     a00, q0.x);
                fma2(accA[2 * j + 1], a00, q0.y);
                fma2(accB[2 * j],     a10, q0.x);
                fma2(accB[2 * j + 1], a10, q0.y);
                ulonglong2 q1 = b1[j];
                fma2(accA[2 * j],     a01, q1.x);
                fma2(accA[2 * j + 1], a01, q1.y);
                fma2(accB[2 * j],     a11, q1.x);
                fma2(accB[2 * j + 1], a11, q1.y);
            }
        }

        // store next chunk into the OTHER buffer (current one already read)
        if (ch + 1 < NCH) {
            float* as = As + ((ch + 1) & 1) * AS_BUF;
            float* bs = Bs + ((ch + 1) & 1) * BS_BUF;
#pragma unroll
            for (int i = 0; i < 8; i++) {
                int base = (ld_r + i * 16) * AST + ld_k;
                *reinterpret_cast<float2*>(as + base)     = make_float2(pa[i].x, pa[i].y);
                *reinterpret_cast<float2*>(as + base + 2) = make_float2(pa[i].z, pa[i].w);
            }
#pragma unroll
            for (int i = 0; i < 10; i++) bs[tx + i * 128] = pb[i];
            __syncthreads();
        }
    }
}

// ---------- kA: gather [W_cls|W_fl] + fused bias ----------
__global__ void kA_prep(const float* __restrict__ Wc, const float* __restrict__ Wf,
                        const float* __restrict__ be,
                        const float* __restrict__ bc, const float* __restrict__ bf) {
    int i = blockIdx.x * 256 + threadIdx.x;
    if (i < KDIM * NC) {
        int j = i / NC, c = i % NC;
        g_Wcat[i] = (c < NCLS) ? Wc[j * NCLS + c] : Wf[j * NCLS + (c - NCLS)];
    }
    if (blockIdx.x < NC) {
        __shared__ float red[256];
        int c = blockIdx.x, tx = threadIdx.x;
        float acc = 0.f;
        for (int j = tx; j < KDIM; j += 256) {
            float w = (c < NCLS) ? Wc[j * NCLS + c] : Wf[j * NCLS + (c - NCLS)];
            acc += be[j] * w;
        }
        red[tx] = acc;
        __syncthreads();
        for (int s = 128; s > 0; s >>= 1) {
            if (tx < s) red[tx] += red[tx + s];
            __syncthreads();
        }
        if (tx == 0) g_bias[c] = red[0] + ((c < NCLS) ? bc[c] : bf[c - NCLS]);
    }
}

// ---------- k1: partials of W_enc @ Wcat (16 m-tiles x 8 K-splits) ----------
__global__ void __launch_bounds__(128, 1) k1_part(const float* __restrict__ Wenc) {
    extern __shared__ float sm[];
    int tx = threadIdx.x;
    int mt = blockIdx.x & 15;
    int js = blockIdx.x >> 4;
    ull accA[10] = {}, accB[10] = {};
    gemm_core<8>(Wenc + (size_t)mt * TM * KDIM + js * 256,
                 g_Wcat + (size_t)js * 256 * NC, sm, tx, accA, accB);
    int g = tx & 1, r0 = (tx >> 1) * 2, c0 = g * 20;
    ull* d0 = reinterpret_cast<ull*>(g_part[js] + (size_t)(mt * TM + r0) * NC + c0);
    ull* d1 = reinterpret_cast<ull*>(g_part[js] + (size_t)(mt * TM + r0 + 1) * NC + c0);
#pragma unroll
    for (int j = 0; j < 10; j++) { d0[j] = accA[j]; d1[j] = accB[j]; }
}

// ---------- k2: reduce splits (float4, high MLP) ----------
__global__ void k2_reduce() {
    int i4 = blockIdx.x * 256 + threadIdx.x;
    if (i4 < KDIM * NC / 4) {
        float4 s = make_float4(0.f, 0.f, 0.f, 0.f);
#pragma unroll
        for (int t = 0; t < NSPLIT; t++) {
            float4 v = reinterpret_cast<const float4*>(g_part[t])[i4];
            s.x += v.x; s.y += v.y; s.z += v.z; s.w += v.w;
        }
        reinterpret_cast<float4*>(g_Wbig)[i4] = s;
    }
}

// ---------- k3: main GEMM + fused softmax/threshold epilogue ----------
__global__ void __launch_bounds__(128, 1) k3_main(const float* __restrict__ x,
                                                  float* __restrict__ out) {
    extern __shared__ float sm[];
    int tx = threadIdx.x;
    int mt = blockIdx.x;
    ull accA[10] = {}, accB[10] = {};
    gemm_core<KDIM / KC>(x + (size_t)mt * TM * KDIM, g_Wbig, sm, tx, accA, accB);
    __syncthreads();

    float* Ls = sm;  // [128][40]
    int g = tx & 1, r0 = (tx >> 1) * 2, c0 = g * 20;
    const ull* bias2 = reinterpret_cast<const ull*>(g_bias + c0);
    ull* L0 = reinterpret_cast<ull*>(Ls + r0 * NC + c0);
    ull* L1 = reinterpret_cast<ull*>(Ls + (r0 + 1) * NC + c0);
#pragma unroll
    for (int j = 0; j < 10; j++) {
        ull b = bias2[j];
        L0[j] = add2(accA[j], b);
        L1[j] = add2(accB[j], b);
    }
    __syncthreads();

    {
        const float* L = Ls + tx * NC;
        float mc = L[0];
#pragma unroll
        for (int c = 1; c < NCLS; c++) mc = fmaxf(mc, L[c]);
        float p[NCLS];
        float se = 0.f;
#pragma unroll
        for (int c = 0; c < NCLS; c++) { p[c] = expf(L[c] - mc); se += p[c]; }
        float inv = 1.f / se;
        float mf = L[NCLS], mn = L[NCLS];
#pragma unroll
        for (int c = NCLS + 1; c < NC; c++) { mf = fmaxf(mf, L[c]); mn = fminf(mn, L[c]); }
        float sf = 0.f;
#pragma unroll
        for (int c = NCLS; c < NC; c++) sf += expf(L[c] - mf);
        float tau = expf(mn - mf) / sf;
        float scale = (inv >= tau + S_MARGIN) ? inv : 0.f;

        float4* o4 = reinterpret_cast<float4*>(out + (size_t)(mt * TM + tx) * NCLS);
#pragma unroll
        for (int q = 0; q < 5; q++)
            o4[q] = make_float4(p[4 * q] * scale, p[4 * q + 1] * scale,
                                p[4 * q + 2] * scale, p[4 * q + 3] * scale);
    }
}

extern "C" void kernel_launch(void* const* d_in, const int* in_sizes, int n_in,
                              void* d_out, int out_size) {
    const float* x    = (const float*)d_in[0];
    const float* Wenc = (const float*)d_in[1];
    const float* benc = (const float*)d_in[2];
    const float* Wcls = (const float*)d_in[3];
    const float* bcls = (const float*)d_in[4];
    const float* Wfl  = (const float*)d_in[5];
    const float* bfl  = (const float*)d_in[6];
    float* out = (float*)d_out;

    const int smem = SMEM_FLOATS * (int)sizeof(float);  // 45056 B
    cudaFuncSetAttribute(k1_part, cudaFuncAttributeMaxDynamicSharedMemorySize, smem);
    cudaFuncSetAttribute(k3_main, cudaFuncAttributeMaxDynamicSharedMemorySize, smem);

    kA_prep<<<(KDIM * NC + 255) / 256, 256>>>(Wcls, Wfl, benc, bcls, bfl);
    k1_part<<<128, 128, smem>>>(Wenc);
    k2_reduce<<<(KDIM * NC / 4 + 255) / 256, 256>>>();
    k3_main<<<128, 128, smem>>>(x, out);   // launch #6 overall -> ncu captures this
}

// round 4
// speedup vs baseline: 1.5000x; 1.0721x over previous
#include <cuda_runtime.h>
#include <cstdint>

#define M_ROWS 16384
#define KDIM   2048
#define NC     40
#define NCLS   20
#define TM     128
#define KC     32
#define NSPLIT 8
#define S_MARGIN 0.31f

typedef unsigned long long ull;

__device__ float g_Wcat[KDIM * NC];
__device__ float g_bias[NC];
__device__ float g_part[NSPLIT][KDIM * NC];
__device__ float g_Wbig[KDIM * NC];

// ---------- packed f32x2 helpers ----------
__device__ __forceinline__ ull pack2(float a, float b) {
    ull r; asm("mov.b64 %0, {%1, %2};" : "=l"(r) : "f"(a), "f"(b)); return r;
}
__device__ __forceinline__ void unpack2(ull v, float& a, float& b) {
    asm("mov.b64 {%0, %1}, %2;" : "=f"(a), "=f"(b) : "l"(v));
}
__device__ __forceinline__ void fma2(ull& acc, ull a, ull b) {
    asm("fma.rn.f32x2 %0, %1, %2, %0;" : "+l"(acc) : "l"(a), "l"(b));
}

// ---------- smem layout ----------
#define AST 34
#define AS_BUF (TM * AST)                 // 4352 floats
#define BS_BUF (KC * NC)                  // 1280 floats
#define GEMM_SMEM (2 * AS_BUF + 2 * BS_BUF)   // 11264 floats
#define LSTRIDE 41                        // padded row stride (conflict-free)
#define LREG (TM * LSTRIDE)               // 5248 floats per ksplit region
#define EPI_SMEM (4 * LREG)               // 20992 floats
#define SMEM_FLOATS (EPI_SMEM)            // 83968 B (> GEMM_SMEM)

// C[128 x 40] = A[128 x NCH*32] @ B[NCH*32 x 40], 256 threads.
// Thread: 4 rows (rg, rg+32, rg+64, rg+96) x 20 cols, over 8 of each 32-k chunk.
// acc[i*10 + j] = (row rg+32i, col c0+2j..2j+1) partial over this thread's k's.
template <int NCH>
__device__ __forceinline__ void gemm_core(
    const float* __restrict__ A,   // row-major, ld = KDIM
    const float* __restrict__ B,   // [k][40]
    float* sm, int tx, ull acc[40])
{
    float* As = sm;
    float* Bs = sm + 2 * AS_BUF;

    const int ld_r = tx >> 3;            // 0..31
    const int ld_k = (tx & 7) << 2;      // 0..28
    const int rg = tx & 31;              // rowgroup: rows rg + 32*i
    const int cg = (tx >> 5) & 1;        // col group
    const int ks = tx >> 6;              // k-split 0..3
    const int c0 = cg * 20;
    const int k0 = ks * 8;

    float4 pa[4];
    float  pb[5];

    // prefetch + store chunk 0
#pragma unroll
    for (int i = 0; i < 4; i++)
        pa[i] = *reinterpret_cast<const float4*>(A + (size_t)(ld_r + 32 * i) * KDIM + ld_k);
#pragma unroll
    for (int i = 0; i < 5; i++)
        pb[i] = B[tx + 256 * i];
#pragma unroll
    for (int i = 0; i < 4; i++) {
        int base = (ld_r + 32 * i) * AST + ld_k;
        *reinterpret_cast<float2*>(As + base)     = make_float2(pa[i].x, pa[i].y);
        *reinterpret_cast<float2*>(As + base + 2) = make_float2(pa[i].z, pa[i].w);
    }
#pragma unroll
    for (int i = 0; i < 5; i++) Bs[tx + 256 * i] = pb[i];
    __syncthreads();

#pragma unroll 1
    for (int ch = 0; ch < NCH; ch++) {
        if (ch + 1 < NCH) {
            const int kc = (ch + 1) * KC;
#pragma unroll
            for (int i = 0; i < 4; i++)
                pa[i] = *reinterpret_cast<const float4*>(A + (size_t)(ld_r + 32 * i) * KDIM + kc + ld_k);
#pragma unroll
            for (int i = 0; i < 5; i++)
                pb[i] = B[kc * NC + tx + 256 * i];
        }

        const float* ab = As + (ch & 1) * AS_BUF + rg * AST + k0;
        const float* bb = Bs + (ch & 1) * BS_BUF + k0 * NC + c0;

#pragma unroll
        for (int k2 = 0; k2 < 4; k2++) {
            float2 av[4];
#pragma unroll
            for (int i = 0; i < 4; i++)
                av[i] = *reinterpret_cast<const float2*>(ab + i * 32 * AST + 2 * k2);
            ull ae[4], ao[4];
#pragma unroll
            for (int i = 0; i < 4; i++) {
                ae[i] = pack2(av[i].x, av[i].x);
                ao[i] = pack2(av[i].y, av[i].y);
            }
            const ulonglong2* b0 = reinterpret_cast<const ulonglong2*>(bb + (2 * k2) * NC);
            const ulonglong2* b1 = reinterpret_cast<const ulonglong2*>(bb + (2 * k2 + 1) * NC);
#pragma unroll
            for (int j = 0; j < 5; j++) {
                ulonglong2 q0 = b0[j];
                ulonglong2 q1 = b1[j];
#pragma unroll
                for (int i = 0; i < 4; i++) {
                    fma2(acc[i * 10 + 2 * j],     ae[i], q0.x);
                    fma2(acc[i * 10 + 2 * j + 1], ae[i], q0.y);
                }
#pragma unroll
                for (int i = 0; i < 4; i++) {
                    fma2(acc[i * 10 + 2 * j],     ao[i], q1.x);
                    fma2(acc[i * 10 + 2 * j + 1], ao[i], q1.y);
                }
            }
        }

        if (ch + 1 < NCH) {
            float* as = As + ((ch + 1) & 1) * AS_BUF;
            float* bs = Bs + ((ch + 1) & 1) * BS_BUF;
#pragma unroll
            for (int i = 0; i < 4; i++) {
                int base = (ld_r + 32 * i) * AST + ld_k;
                *reinterpret_cast<float2*>(as + base)     = make_float2(pa[i].x, pa[i].y);
                *reinterpret_cast<float2*>(as + base + 2) = make_float2(pa[i].z, pa[i].w);
            }
#pragma unroll
            for (int i = 0; i < 5; i++) bs[tx + 256 * i] = pb[i];
            __syncthreads();
        }
    }
}

// Write this thread's partials into its ksplit region of smem.
__device__ __forceinline__ void dump_partials(float* sm, int tx, const ull acc[40]) {
    const int rg = tx & 31, cg = (tx >> 5) & 1, ks = tx >> 6;
    float* R = sm + ks * LREG;
#pragma unroll
    for (int i = 0; i < 4; i++) {
        float* row = R + (rg + 32 * i) * LSTRIDE + cg * 20;
#pragma unroll
        for (int j = 0; j < 10; j++) {
            float lo, hi;
            unpack2(acc[i * 10 + j], lo, hi);
            row[2 * j] = lo; row[2 * j + 1] = hi;
        }
    }
}

// ---------- kA: gather [W_cls|W_fl] + fused bias ----------
__global__ void kA_prep(const float* __restrict__ Wc, const float* __restrict__ Wf,
                        const float* __restrict__ be,
                        const float* __restrict__ bc, const float* __restrict__ bf) {
    int i = blockIdx.x * 256 + threadIdx.x;
    if (i < KDIM * NC) {
        int j = i / NC, c = i % NC;
        g_Wcat[i] = (c < NCLS) ? Wc[j * NCLS + c] : Wf[j * NCLS + (c - NCLS)];
    }
    if (blockIdx.x < NC) {
        __shared__ float red[256];
        int c = blockIdx.x, tx = threadIdx.x;
        float acc = 0.f;
        for (int j = tx; j < KDIM; j += 256) {
            float w = (c < NCLS) ? Wc[j * NCLS + c] : Wf[j * NCLS + (c - NCLS)];
            acc += be[j] * w;
        }
        red[tx] = acc;
        __syncthreads();
        for (int s = 128; s > 0; s >>= 1) {
            if (tx < s) red[tx] += red[tx + s];
            __syncthreads();
        }
        if (tx == 0) g_bias[c] = red[0] + ((c < NCLS) ? bc[c] : bf[c - NCLS]);
    }
}

// ---------- k1: partials of W_enc @ Wcat (16 m-tiles x 8 K-splits) ----------
__global__ void __launch_bounds__(256, 1) k1_part(const float* __restrict__ Wenc) {
    extern __shared__ float sm[];
    int tx = threadIdx.x;
    int mt = blockIdx.x & 15;
    int js = blockIdx.x >> 4;
    ull acc[40] = {};
    gemm_core<8>(Wenc + (size_t)mt * TM * KDIM + js * 256,
                 g_Wcat + (size_t)js * 256 * NC, sm, tx, acc);
    __syncthreads();
    dump_partials(sm, tx, acc);
    __syncthreads();
    if (tx < TM) {
        float4* dst = reinterpret_cast<float4*>(g_part[js] + (size_t)(mt * TM + tx) * NC);
        const float* L0 = sm + tx * LSTRIDE;
#pragma unroll
        for (int q = 0; q < 10; q++) {
            float4 v;
            v.x = L0[4*q]   + L0[LREG + 4*q]   + L0[2*LREG + 4*q]   + L0[3*LREG + 4*q];
            v.y = L0[4*q+1] + L0[LREG + 4*q+1] + L0[2*LREG + 4*q+1] + L0[3*LREG + 4*q+1];
            v.z = L0[4*q+2] + L0[LREG + 4*q+2] + L0[2*LREG + 4*q+2] + L0[3*LREG + 4*q+2];
            v.w = L0[4*q+3] + L0[LREG + 4*q+3] + L0[2*LREG + 4*q+3] + L0[3*LREG + 4*q+3];
            dst[q] = v;
        }
    }
}

// ---------- k2: reduce splits ----------
__global__ void k2_reduce() {
    int i4 = blockIdx.x * 256 + threadIdx.x;
    if (i4 < KDIM * NC / 4) {
        float4 s = make_float4(0.f, 0.f, 0.f, 0.f);
#pragma unroll
        for (int t = 0; t < NSPLIT; t++) {
            float4 v = reinterpret_cast<const float4*>(g_part[t])[i4];
            s.x += v.x; s.y += v.y; s.z += v.z; s.w += v.w;
        }
        reinterpret_cast<float4*>(g_Wbig)[i4] = s;
    }
}

// ---------- k3: main GEMM + fused softmax/threshold epilogue ----------
__global__ void __launch_bounds__(256, 1) k3_main(const float* __restrict__ x,
                                                  float* __restrict__ out) {
    extern __shared__ float sm[];
    int tx = threadIdx.x;
    int mt = blockIdx.x;
    ull acc[40] = {};
    gemm_core<KDIM / KC>(x + (size_t)mt * TM * KDIM, g_Wbig, sm, tx, acc);
    __syncthreads();
    dump_partials(sm, tx, acc);
    __syncthreads();

    if (tx < TM) {
        const float* L0 = sm + tx * LSTRIDE;
        float L[NC];
#pragma unroll
        for (int c = 0; c < NC; c++)
            L[c] = g_bias[c] + L0[c] + L0[LREG + c] + L0[2 * LREG + c] + L0[3 * LREG + c];

        float mc = L[0];
#pragma unroll
        for (int c = 1; c < NCLS; c++) mc = fmaxf(mc, L[c]);
        float p[NCLS];
        float se = 0.f;
#pragma unroll
        for (int c = 0; c < NCLS; c++) { p[c] = expf(L[c] - mc); se += p[c]; }
        float inv = 1.f / se;
        float mf = L[NCLS], mn = L[NCLS];
#pragma unroll
        for (int c = NCLS + 1; c < NC; c++) { mf = fmaxf(mf, L[c]); mn = fminf(mn, L[c]); }
        float sf = 0.f;
#pragma unroll
        for (int c = NCLS; c < NC; c++) sf += expf(L[c] - mf);
        float tau = expf(mn - mf) / sf;
        float scale = (inv >= tau + S_MARGIN) ? inv : 0.f;

        float4* o4 = reinterpret_cast<float4*>(out + (size_t)(mt * TM + tx) * NCLS);
#pragma unroll
        for (int q = 0; q < 5; q++)
            o4[q] = make_float4(p[4 * q] * scale, p[4 * q + 1] * scale,
                                p[4 * q + 2] * scale, p[4 * q + 3] * scale);
    }
}

extern "C" void kernel_launch(void* const* d_in, const int* in_sizes, int n_in,
                              void* d_out, int out_size) {
    const float* x    = (const float*)d_in[0];
    const float* Wenc = (const float*)d_in[1];
    const float* benc = (const float*)d_in[2];
    const float* Wcls = (const float*)d_in[3];
    const float* bcls = (const float*)d_in[4];
    const float* Wfl  = (const float*)d_in[5];
    const float* bfl  = (const float*)d_in[6];
    float* out = (float*)d_out;

    const int smem = SMEM_FLOATS * (int)sizeof(float);  // 83968 B
    cudaFuncSetAttribute(k1_part, cudaFuncAttributeMaxDynamicSharedMemorySize, smem);
    cudaFuncSetAttribute(k3_main, cudaFuncAttributeMaxDynamicSharedMemorySize, smem);

    kA_prep<<<(KDIM * NC + 255) / 256, 256>>>(Wcls, Wfl, benc, bcls, bfl);
    k1_part<<<128, 256, smem>>>(Wenc);
    k2_reduce<<<(KDIM * NC / 4 + 255) / 256, 256>>>();
    k3_main<<<128, 256, smem>>>(x, out);   // launch #6 -> ncu captures this
}